// round 3
// baseline (speedup 1.0000x reference)
#include <cuda_runtime.h>
#include <math.h>

// Problem constants
#define BDIM   4
#define SEQ    2048
#define DMODEL 1024
#define NH     16
#define HD     64
#define SCALE  0.125f            // 1/sqrt(64)
#define M_ROWS (BDIM*SEQ)        // 8192

typedef unsigned long long u64;

// ---- packed f32x2 helpers (Blackwell sm_103a) ----
__device__ __forceinline__ u64 pack2(float lo, float hi) {
    u64 r; asm("mov.b64 %0, {%1,%2};" : "=l"(r) : "f"(lo), "f"(hi)); return r;
}
__device__ __forceinline__ float2 unpack2(u64 v) {
    float2 r; asm("mov.b64 {%0,%1}, %2;" : "=f"(r.x), "=f"(r.y) : "l"(v)); return r;
}
__device__ __forceinline__ void ffma2(u64& c, u64 a, u64 b) {
    asm("fma.rn.f32x2 %0, %1, %2, %3;" : "=l"(c) : "l"(a), "l"(b), "l"(c));
}
__device__ __forceinline__ u64 mul2(u64 a, u64 b) {
    u64 r; asm("mul.rn.f32x2 %0, %1, %2;" : "=l"(r) : "l"(a), "l"(b)); return r;
}

// ---- scratch (device globals: no allocation allowed) ----
__device__ float g_q[BDIM*NH*SEQ*HD];      // [B,H,S,hd], pre-scaled by SCALE
__device__ float g_k[BDIM*NH*SEQ*HD];      // [B,H,S,hd]
__device__ float g_v[BDIM*NH*SEQ*HD];      // [B,H,S,hd]
__device__ float g_attn[BDIM*SEQ*DMODEL];  // [B,S,D]

// ============================================================================
// Kernel 1: qkv = x @ W_qkv + b_qkv, scattered to q/k/v in [B,H,S,hd]
// C is [8192, 3072]. Tiles: BM=128, BN=128, BK=16; 256 threads, 8x8/thread.
// ============================================================================
__global__ __launch_bounds__(256) void qkv_gemm(
    const float* __restrict__ X, const float* __restrict__ W,
    const float* __restrict__ bias)
{
    __shared__ __align__(16) float As[16][128];   // [k][m]
    __shared__ __align__(16) float Bs[16][128];   // [k][n]

    const int tid = threadIdx.x;
    const int bm = blockIdx.y * 128;
    const int bn = blockIdx.x * 128;
    const int tx = tid & 15, ty = tid >> 4;

    u64 acc[8][4];
    #pragma unroll
    for (int i = 0; i < 8; i++)
        #pragma unroll
        for (int j = 0; j < 4; j++) acc[i][j] = 0ull;

    for (int k0 = 0; k0 < 1024; k0 += 16) {
        // A tile: 128 rows x 16 k, stored transposed. 512 float4, 2/thread.
        #pragma unroll
        for (int r = 0; r < 2; r++) {
            int i = tid + (r << 8);
            int row = i >> 2, cv = (i & 3) << 2;
            float4 v = *(const float4*)(X + (size_t)(bm + row) * 1024 + k0 + cv);
            As[cv  ][row] = v.x; As[cv+1][row] = v.y;
            As[cv+2][row] = v.z; As[cv+3][row] = v.w;
        }
        // B tile: 16 k x 128 n. 512 float4, 2/thread.
        #pragma unroll
        for (int r = 0; r < 2; r++) {
            int i = tid + (r << 8);
            int rk = i >> 5, col = (i & 31) << 2;
            *(float4*)&Bs[rk][col] =
                *(const float4*)(W + (size_t)(k0 + rk) * 3072 + bn + col);
        }
        __syncthreads();

        #pragma unroll
        for (int kk = 0; kk < 16; kk++) {
            u64 b2[4];
            #pragma unroll
            for (int j = 0; j < 4; j++)
                b2[j] = *(const u64*)&Bs[kk][tx * 8 + j * 2];
            float4 a0 = *(const float4*)&As[kk][ty * 8];
            float4 a1 = *(const float4*)&As[kk][ty * 8 + 4];
            float a[8] = {a0.x, a0.y, a0.z, a0.w, a1.x, a1.y, a1.z, a1.w};
            #pragma unroll
            for (int i = 0; i < 8; i++) {
                u64 a2 = pack2(a[i], a[i]);
                #pragma unroll
                for (int j = 0; j < 4; j++) ffma2(acc[i][j], a2, b2[j]);
            }
        }
        __syncthreads();
    }

    // epilogue: bias add + scatter to q/k/v [B,H,S,hd]; q pre-scaled
    #pragma unroll
    for (int i = 0; i < 8; i++) {
        int m = bm + ty * 8 + i;
        int b = m >> 11, s = m & 2047;
        #pragma unroll
        for (int j = 0; j < 4; j++) {
            float2 v = unpack2(acc[i][j]);
            #pragma unroll
            for (int e = 0; e < 2; e++) {
                int n = bn + tx * 8 + j * 2 + e;
                float val = (e ? v.y : v.x) + bias[n];
                int w = n >> 10, h = (n >> 6) & 15, d = n & 63;
                size_t idx = ((size_t)(b * NH + h) * SEQ + s) * HD + d;
                if (w == 0)      g_q[idx] = val * SCALE;
                else if (w == 1) g_k[idx] = val;
                else             g_v[idx] = val;
            }
        }
    }
}

// ============================================================================
// Kernel 2: flash attention. Grid (B*H, S/64). 256 threads.
// Q tile 64x64 in smem; loop over 32 KV tiles of 64; online softmax.
// Output written to g_attn in [B,S,D] layout.
// Strides: Kts/Ps rows = 66 floats (u64-safe), Vs rows = 68 floats
// (float4-safe: 68 % 4 == 0 so row*68+4c is 16B aligned).
// ============================================================================
#define BQ  64
#define BKV 64
#define VST 68

__global__ __launch_bounds__(256) void attn_kernel()
{
    extern __shared__ float sm[];
    float (*Qs)[HD]       = (float(*)[HD])      (sm);                  // 4096
    float (*Kts)[BKV + 2] = (float(*)[BKV + 2]) (sm + 4096);           // 4224
    float (*Vs)[VST]      = (float(*)[VST])     (sm + 4096 + 4224);    // 4352
    float (*Ps)[BKV + 2]  = (float(*)[BKV + 2]) (sm + 4096 + 4224 + 4352); // 4224
    float* m_s  = sm + 4096 + 4224 + 4352 + 4224;
    float* l_s  = m_s + 64;
    float* sc_s = l_s + 64;

    const int tid = threadIdx.x;
    const int bh = blockIdx.x;               // b*16 + h
    const int q0 = blockIdx.y * BQ;
    const int tx = tid & 15, ty = tid >> 4;

    const float* Qg = g_q + (size_t)bh * SEQ * HD;
    const float* Kg = g_k + (size_t)bh * SEQ * HD;
    const float* Vg = g_v + (size_t)bh * SEQ * HD;

    // load Q tile (already scaled)
    #pragma unroll
    for (int it = 0; it < 4; it++) {
        int i = tid + (it << 8);
        int row = i >> 4, c4 = (i & 15) << 2;
        *(float4*)&Qs[row][c4] = *(const float4*)(Qg + (size_t)(q0 + row) * HD + c4);
    }
    if (tid < 64) { m_s[tid] = -1e30f; l_s[tid] = 0.f; }

    u64 acc[4][2];
    #pragma unroll
    for (int i = 0; i < 4; i++) { acc[i][0] = 0ull; acc[i][1] = 0ull; }
    __syncthreads();

    for (int t = 0; t < SEQ / BKV; t++) {
        // load K (transposed into [d][j]) and V ([j][d])
        #pragma unroll
        for (int it = 0; it < 4; it++) {
            int i = tid + (it << 8);
            int row = i >> 4, c4 = (i & 15) << 2;
            float4 kv = *(const float4*)(Kg + (size_t)(t * BKV + row) * HD + c4);
            Kts[c4  ][row] = kv.x; Kts[c4+1][row] = kv.y;
            Kts[c4+2][row] = kv.z; Kts[c4+3][row] = kv.w;
            *(float4*)&Vs[row][c4] =
                *(const float4*)(Vg + (size_t)(t * BKV + row) * HD + c4);
        }
        __syncthreads();

        // S = Qs @ K^T  (4 rows x 4 cols per thread)
        u64 s2[4][2];
        #pragma unroll
        for (int i = 0; i < 4; i++) { s2[i][0] = 0ull; s2[i][1] = 0ull; }
        #pragma unroll 4
        for (int d = 0; d < HD; d++) {
            u64 b0 = *(const u64*)&Kts[d][tx * 4];
            u64 b1 = *(const u64*)&Kts[d][tx * 4 + 2];
            #pragma unroll
            for (int i = 0; i < 4; i++) {
                float q = Qs[ty * 4 + i][d];
                u64 a2 = pack2(q, q);
                ffma2(s2[i][0], a2, b0);
                ffma2(s2[i][1], a2, b1);
            }
        }
        #pragma unroll
        for (int i = 0; i < 4; i++) {
            float2 v0 = unpack2(s2[i][0]), v1 = unpack2(s2[i][1]);
            float* pr = &Ps[ty * 4 + i][tx * 4];
            pr[0] = v0.x; pr[1] = v0.y; pr[2] = v1.x; pr[3] = v1.y;
        }
        __syncthreads();

        // online softmax: 4 threads per row, 16 cols each
        {
            int row = tid >> 2, part = tid & 3;
            float* prow = &Ps[row][part * 16];
            float tmax = prow[0];
            #pragma unroll
            for (int c = 1; c < 16; c++) tmax = fmaxf(tmax, prow[c]);
            tmax = fmaxf(tmax, __shfl_xor_sync(0xffffffffu, tmax, 1));
            tmax = fmaxf(tmax, __shfl_xor_sync(0xffffffffu, tmax, 2));
            float m_old = m_s[row];
            float m_new = fmaxf(m_old, tmax);
            float psum = 0.f;
            #pragma unroll
            for (int c = 0; c < 16; c++) {
                float p = __expf(prow[c] - m_new);
                prow[c] = p;
                psum += p;
            }
            psum += __shfl_xor_sync(0xffffffffu, psum, 1);
            psum += __shfl_xor_sync(0xffffffffu, psum, 2);
            if (part == 0) {
                float f = __expf(m_old - m_new);
                sc_s[row] = f;
                l_s[row] = l_s[row] * f + psum;
                m_s[row] = m_new;
            }
        }
        __syncthreads();

        // rescale running O, then O += P @ V
        #pragma unroll
        for (int i = 0; i < 4; i++) {
            float f = sc_s[ty * 4 + i];
            u64 f2 = pack2(f, f);
            acc[i][0] = mul2(acc[i][0], f2);
            acc[i][1] = mul2(acc[i][1], f2);
        }
        #pragma unroll 4
        for (int j = 0; j < BKV; j++) {
            u64 b0 = *(const u64*)&Vs[j][tx * 4];
            u64 b1 = *(const u64*)&Vs[j][tx * 4 + 2];
            #pragma unroll
            for (int i = 0; i < 4; i++) {
                float p = Ps[ty * 4 + i][j];
                u64 a2 = pack2(p, p);
                ffma2(acc[i][0], a2, b0);
                ffma2(acc[i][1], a2, b1);
            }
        }
        __syncthreads();
    }

    // epilogue: divide by l, write [B,S,D]
    const int b = bh >> 4, h = bh & 15;
    #pragma unroll
    for (int i = 0; i < 4; i++) {
        float inv = 1.f / l_s[ty * 4 + i];
        int srow = q0 + ty * 4 + i;
        float* dst = g_attn + (size_t)(b * SEQ + srow) * DMODEL + h * HD + tx * 4;
        float2 v0 = unpack2(acc[i][0]);
        float2 v1 = unpack2(acc[i][1]);
        dst[0] = v0.x * inv; dst[1] = v0.y * inv;
        dst[2] = v1.x * inv; dst[3] = v1.y * inv;
    }
}

// ============================================================================
// Kernel 3: out = g_attn @ W_proj + b_proj.  C is [8192, 1024].
// ============================================================================
__global__ __launch_bounds__(256) void proj_gemm(
    const float* __restrict__ W, const float* __restrict__ bias,
    float* __restrict__ out)
{
    __shared__ __align__(16) float As[16][128];
    __shared__ __align__(16) float Bs[16][128];

    const int tid = threadIdx.x;
    const int bm = blockIdx.y * 128;
    const int bn = blockIdx.x * 128;
    const int tx = tid & 15, ty = tid >> 4;

    u64 acc[8][4];
    #pragma unroll
    for (int i = 0; i < 8; i++)
        #pragma unroll
        for (int j = 0; j < 4; j++) acc[i][j] = 0ull;

    for (int k0 = 0; k0 < 1024; k0 += 16) {
        #pragma unroll
        for (int r = 0; r < 2; r++) {
            int i = tid + (r << 8);
            int row = i >> 2, cv = (i & 3) << 2;
            float4 v = *(const float4*)(g_attn + (size_t)(bm + row) * 1024 + k0 + cv);
            As[cv  ][row] = v.x; As[cv+1][row] = v.y;
            As[cv+2][row] = v.z; As[cv+3][row] = v.w;
        }
        #pragma unroll
        for (int r = 0; r < 2; r++) {
            int i = tid + (r << 8);
            int rk = i >> 5, col = (i & 31) << 2;
            *(float4*)&Bs[rk][col] =
                *(const float4*)(W + (size_t)(k0 + rk) * 1024 + bn + col);
        }
        __syncthreads();

        #pragma unroll
        for (int kk = 0; kk < 16; kk++) {
            u64 b2[4];
            #pragma unroll
            for (int j = 0; j < 4; j++)
                b2[j] = *(const u64*)&Bs[kk][tx * 8 + j * 2];
            float4 a0 = *(const float4*)&As[kk][ty * 8];
            float4 a1 = *(const float4*)&As[kk][ty * 8 + 4];
            float a[8] = {a0.x, a0.y, a0.z, a0.w, a1.x, a1.y, a1.z, a1.w};
            #pragma unroll
            for (int i = 0; i < 8; i++) {
                u64 a2 = pack2(a[i], a[i]);
                #pragma unroll
                for (int j = 0; j < 4; j++) ffma2(acc[i][j], a2, b2[j]);
            }
        }
        __syncthreads();
    }

    #pragma unroll
    for (int i = 0; i < 8; i++) {
        int m = bm + ty * 8 + i;
        #pragma unroll
        for (int j = 0; j < 4; j++) {
            float2 v = unpack2(acc[i][j]);
            int n = bn + tx * 8 + j * 2;
            out[(size_t)m * 1024 + n]     = v.x + bias[n];
            out[(size_t)m * 1024 + n + 1] = v.y + bias[n + 1];
        }
    }
}

// ============================================================================
extern "C" void kernel_launch(void* const* d_in, const int* in_sizes, int n_in,
                              void* d_out, int out_size)
{
    const float* x      = (const float*)d_in[0];
    const float* W_qkv  = (const float*)d_in[1];
    const float* b_qkv  = (const float*)d_in[2];
    const float* W_proj = (const float*)d_in[3];
    const float* b_proj = (const float*)d_in[4];
    float* out = (float*)d_out;

    // Qs 4096 + Kts 4224 + Vs 4352 + Ps 4224 + 192 = 17088 floats
    const int attn_smem = 17088 * (int)sizeof(float); // 68352 B
    cudaFuncSetAttribute(attn_kernel,
                         cudaFuncAttributeMaxDynamicSharedMemorySize, attn_smem);

    qkv_gemm<<<dim3(24, 64), 256>>>(x, W_qkv, b_qkv);
    attn_kernel<<<dim3(64, 32), 256, attn_smem>>>();
    proj_gemm<<<dim3(8, 64), 256>>>(W_proj, b_proj, out);
}

// round 5
// speedup vs baseline: 2.6249x; 2.6249x over previous
#include <cuda_runtime.h>
#include <cuda_bf16.h>
#include <math.h>
#include <cstdint>

// Problem constants
#define BDIM   4
#define SEQ    2048
#define DMODEL 1024
#define NH     16
#define HD     64
#define SCALE  0.125f            // 1/sqrt(64)

// ============================================================================
// mma.sync / ldmatrix helpers (base sm_80+ PTX — safe for compute_103 target)
// ============================================================================
__device__ __forceinline__ void mma16816(float* c, const uint32_t* a, const uint32_t* b) {
    asm volatile("mma.sync.aligned.m16n8k16.row.col.f32.bf16.bf16.f32 "
        "{%0,%1,%2,%3}, {%4,%5,%6,%7}, {%8,%9}, {%0,%1,%2,%3};"
        : "+f"(c[0]), "+f"(c[1]), "+f"(c[2]), "+f"(c[3])
        : "r"(a[0]), "r"(a[1]), "r"(a[2]), "r"(a[3]), "r"(b[0]), "r"(b[1]));
}
__device__ __forceinline__ void ldsm4(uint32_t* r, uint32_t addr) {
    asm volatile("ldmatrix.sync.aligned.m8n8.x4.shared.b16 {%0,%1,%2,%3}, [%4];"
        : "=r"(r[0]), "=r"(r[1]), "=r"(r[2]), "=r"(r[3]) : "r"(addr));
}
__device__ __forceinline__ void ldsm4t(uint32_t* r, uint32_t addr) {
    asm volatile("ldmatrix.sync.aligned.m8n8.x4.trans.shared.b16 {%0,%1,%2,%3}, [%4];"
        : "=r"(r[0]), "=r"(r[1]), "=r"(r[2]), "=r"(r[3]) : "r"(addr));
}
__device__ __forceinline__ uint32_t smem_u32(const void* p) {
    uint32_t a;
    asm("{ .reg .u64 t; cvta.to.shared.u64 t, %1; cvt.u32.u64 %0, t; }"
        : "=r"(a) : "l"(p));
    return a;
}
__device__ __forceinline__ uint32_t bfpair(float x, float y) {
    __nv_bfloat162 p;
    p.x = __float2bfloat16(x); p.y = __float2bfloat16(y);
    return *(uint32_t*)&p;
}

// ============================================================================
// scratch (device globals: no allocation allowed)
// ============================================================================
__device__ __nv_bfloat16 g_xh [8192*1024];   // X hi
__device__ __nv_bfloat16 g_xl [8192*1024];   // X lo
__device__ __nv_bfloat16 g_wqh[3072*1024];   // W_qkv^T hi  [N,K]
__device__ __nv_bfloat16 g_wql[3072*1024];
__device__ __nv_bfloat16 g_wph[1024*1024];   // W_proj^T hi [N,K]
__device__ __nv_bfloat16 g_wpl[1024*1024];
__device__ __nv_bfloat16 g_qh[BDIM*NH*SEQ*HD];  // q hi (pre-scaled), [B,H,S,hd]
__device__ __nv_bfloat16 g_ql[BDIM*NH*SEQ*HD];
__device__ __nv_bfloat16 g_kh[BDIM*NH*SEQ*HD];
__device__ __nv_bfloat16 g_kl[BDIM*NH*SEQ*HD];
__device__ __nv_bfloat16 g_vh[BDIM*NH*SEQ*HD];
__device__ __nv_bfloat16 g_vl[BDIM*NH*SEQ*HD];
__device__ __nv_bfloat16 g_ah[8192*1024];    // attn out hi [B,S,D]
__device__ __nv_bfloat16 g_al[8192*1024];

// ============================================================================
// Pre-pass: split X into bf16 hi/lo
// ============================================================================
__global__ __launch_bounds__(256) void split_x(const float* __restrict__ x,
                                               __nv_bfloat16* __restrict__ dh,
                                               __nv_bfloat16* __restrict__ dl)
{
    size_t i = ((size_t)blockIdx.x * 256 + threadIdx.x) * 4;
    float4 v = *(const float4*)(x + i);
    __nv_bfloat16 h0 = __float2bfloat16(v.x);
    __nv_bfloat16 h1 = __float2bfloat16(v.y);
    __nv_bfloat16 h2 = __float2bfloat16(v.z);
    __nv_bfloat16 h3 = __float2bfloat16(v.w);
    __nv_bfloat162 h01, h23, l01, l23;
    h01.x = h0; h01.y = h1; h23.x = h2; h23.y = h3;
    l01.x = __float2bfloat16(v.x - __bfloat162float(h0));
    l01.y = __float2bfloat16(v.y - __bfloat162float(h1));
    l23.x = __float2bfloat16(v.z - __bfloat162float(h2));
    l23.y = __float2bfloat16(v.w - __bfloat162float(h3));
    *(__nv_bfloat162*)(dh + i)     = h01;
    *(__nv_bfloat162*)(dh + i + 2) = h23;
    *(__nv_bfloat162*)(dl + i)     = l01;
    *(__nv_bfloat162*)(dl + i + 2) = l23;
}

// ============================================================================
// Pre-pass: transpose + split W [K=1024, N] -> W^T hi/lo [N, 1024]
// ============================================================================
__global__ __launch_bounds__(256) void split_tr(const float* __restrict__ src,
                                                __nv_bfloat16* __restrict__ dh,
                                                __nv_bfloat16* __restrict__ dl,
                                                int N)
{
    __shared__ float t[32][33];
    const int n0 = blockIdx.x * 32, k0 = blockIdx.y * 32;
    const int tx = threadIdx.x & 31, ty = threadIdx.x >> 5;   // ty 0..7
    #pragma unroll
    for (int r = 0; r < 4; r++) {
        int k = k0 + ty + r * 8;
        t[ty + r * 8][tx] = src[(size_t)k * N + n0 + tx];
    }
    __syncthreads();
    #pragma unroll
    for (int r = 0; r < 4; r++) {
        int n = n0 + ty + r * 8;
        float v = t[tx][ty + r * 8];
        __nv_bfloat16 h = __float2bfloat16(v);
        dh[(size_t)n * 1024 + k0 + tx] = h;
        dl[(size_t)n * 1024 + k0 + tx] = __float2bfloat16(v - __bfloat162float(h));
    }
}

// ============================================================================
// GEMM via mma.sync: C[128,128] = A[M,1024] @ B^T, split-bf16 (hh+hl+lh).
// 256 threads = 8 warps (2M x 4N); per-warp 64x32; BK=32, double-buffered.
// EPI 0: QKV scatter (bf16 hi/lo q/k/v). EPI 1: proj fp32 out + bias.
// ============================================================================
#define GST   80                  // smem row stride bytes (40 bf16)
#define GTILE (128*GST)           // 10240
#define GSTAGE (4*GTILE)          // 40960 (Ah,Al,Bh,Bl)
#define SMEM_GEMM (2*GSTAGE)      // 81920

__device__ __forceinline__ void g_ldg(const __nv_bfloat16* __restrict__ g,
                                      int rb, int c, int tid, uint4* r)
{
    #pragma unroll
    for (int t = 0; t < 2; t++) {
        int idx = tid + (t << 8);
        int row = idx >> 2, c4 = idx & 3;
        r[t] = *(const uint4*)(g + (size_t)(rb + row) * 1024 + c * 32 + c4 * 8);
    }
}
__device__ __forceinline__ void g_sts(char* tile, int tid, const uint4* r)
{
    #pragma unroll
    for (int t = 0; t < 2; t++) {
        int idx = tid + (t << 8);
        int row = idx >> 2, c4 = idx & 3;
        *(uint4*)(tile + row * GST + c4 * 16) = r[t];
    }
}

template<int EPI>
__global__ __launch_bounds__(256)
void gemm_mma(const __nv_bfloat16* __restrict__ Ah_g, const __nv_bfloat16* __restrict__ Al_g,
              const __nv_bfloat16* __restrict__ Bh_g, const __nv_bfloat16* __restrict__ Bl_g,
              const float* __restrict__ bias, float* __restrict__ out)
{
    extern __shared__ char smem[];
    const uint32_t sb = smem_u32(smem);
    const int tid = threadIdx.x, lane = tid & 31, wid = tid >> 5;
    const int bm = blockIdx.y * 128, bn = blockIdx.x * 128;
    const int wm = (wid >> 2) * 64, wn = (wid & 3) * 32;

    float acc[4][4][4];
    #pragma unroll
    for (int i = 0; i < 4; i++)
        #pragma unroll
        for (int j = 0; j < 4; j++)
            #pragma unroll
            for (int e = 0; e < 4; e++) acc[i][j][e] = 0.f;

    uint4 rg[4][2];
    g_ldg(Ah_g, bm, 0, tid, rg[0]); g_ldg(Al_g, bm, 0, tid, rg[1]);
    g_ldg(Bh_g, bn, 0, tid, rg[2]); g_ldg(Bl_g, bn, 0, tid, rg[3]);
    g_sts(smem + 0*GTILE, tid, rg[0]); g_sts(smem + 1*GTILE, tid, rg[1]);
    g_sts(smem + 2*GTILE, tid, rg[2]); g_sts(smem + 3*GTILE, tid, rg[3]);
    __syncthreads();

    for (int c = 0; c < 32; c++) {
        const int stg = c & 1;
        if (c < 31) {
            g_ldg(Ah_g, bm, c + 1, tid, rg[0]); g_ldg(Al_g, bm, c + 1, tid, rg[1]);
            g_ldg(Bh_g, bn, c + 1, tid, rg[2]); g_ldg(Bl_g, bn, c + 1, tid, rg[3]);
        }
        const uint32_t base = sb + stg * GSTAGE;
        #pragma unroll
        for (int ks = 0; ks < 2; ks++) {
            const int k0 = ks * 16;
            uint32_t bfh[8], bfl[8];
            #pragma unroll
            for (int np = 0; np < 2; np++) {
                int nrow = wn + np*16 + (lane & 7) + ((lane >> 4) & 1) * 8;
                int kcol = k0 + ((lane >> 3) & 1) * 8;
                uint32_t a = base + 2*GTILE + nrow * GST + kcol * 2;
                ldsm4(&bfh[np*4], a);
                ldsm4(&bfl[np*4], a + GTILE);
            }
            #pragma unroll
            for (int mt = 0; mt < 4; mt++) {
                int arow = wm + mt*16 + (lane & 15);
                int acol = k0 + (lane >> 4) * 8;
                uint32_t aa = base + arow * GST + acol * 2;
                uint32_t afh[4], afl[4];
                ldsm4(afh, aa);
                ldsm4(afl, aa + GTILE);
                #pragma unroll
                for (int nt = 0; nt < 4; nt++) {
                    mma16816(acc[mt][nt], afh, &bfh[nt*2]);
                    mma16816(acc[mt][nt], afh, &bfl[nt*2]);
                    mma16816(acc[mt][nt], afl, &bfh[nt*2]);
                }
            }
        }
        if (c < 31) {
            char* t2 = smem + (stg ^ 1) * GSTAGE;
            g_sts(t2 + 0*GTILE, tid, rg[0]); g_sts(t2 + 1*GTILE, tid, rg[1]);
            g_sts(t2 + 2*GTILE, tid, rg[2]); g_sts(t2 + 3*GTILE, tid, rg[3]);
        }
        __syncthreads();
    }

    // epilogue
    #pragma unroll
    for (int mt = 0; mt < 4; mt++) {
        #pragma unroll
        for (int nt = 0; nt < 4; nt++) {
            float* cc = acc[mt][nt];
            int ng = bn + wn + nt*8 + (lane & 3) * 2;
            float2 bb = *(const float2*)(bias + ng);
            #pragma unroll
            for (int rh = 0; rh < 2; rh++) {
                int m = bm + wm + mt*16 + (lane >> 2) + rh * 8;
                float v0 = cc[rh*2] + bb.x, v1 = cc[rh*2+1] + bb.y;
                if (EPI == 0) {
                    int w = ng >> 10, hh = (ng >> 6) & 15, d = ng & 63;
                    int b_ = m >> 11, s = m & 2047;
                    size_t idx = ((size_t)((b_*NH + hh) * SEQ + s)) * HD + d;
                    if (w == 0) { v0 *= SCALE; v1 *= SCALE; }
                    __nv_bfloat16 h0 = __float2bfloat16(v0);
                    __nv_bfloat16 h1 = __float2bfloat16(v1);
                    __nv_bfloat162 hp; hp.x = h0; hp.y = h1;
                    uint32_t lp = bfpair(v0 - __bfloat162float(h0),
                                         v1 - __bfloat162float(h1));
                    __nv_bfloat16* dh = (w == 0) ? g_qh : (w == 1) ? g_kh : g_vh;
                    __nv_bfloat16* dl = (w == 0) ? g_ql : (w == 1) ? g_kl : g_vl;
                    *(uint32_t*)(dh + idx) = *(uint32_t*)&hp;
                    *(uint32_t*)(dl + idx) = lp;
                } else {
                    *(float2*)(out + (size_t)m * 1024 + ng) = make_float2(v0, v1);
                }
            }
        }
    }
}

// ============================================================================
// Flash attention via mma.sync. Grid (B*H=64, S/128=16). 256 thr = 8 warps,
// 16 q-rows/warp. KV tiles of 64. Q frags register-resident; S,P in regs.
// All products split hi/lo (3 MMAs). Output: bf16 hi/lo to g_ah/g_al.
// ============================================================================
#define AST 144                   // smem row stride bytes (72 bf16)
#define QTI (128*AST)             // 18432
#define KTI (64*AST)              // 9216
#define SMEM_ATTN (2*QTI + 4*KTI) // 73728

__global__ __launch_bounds__(256)
void attn_mma()
{
    extern __shared__ char smem[];
    const uint32_t sb = smem_u32(smem);
    const int tid = threadIdx.x, lane = tid & 31, wid = tid >> 5;
    const int bh = blockIdx.x, q0 = blockIdx.y * 128;
    const int b = bh >> 4, h = bh & 15;
    const size_t gq = (size_t)bh * SEQ * HD;

    const uint32_t off_Ql = QTI, off_K = 2*QTI, off_V = 2*QTI + 2*KTI;

    // load Q tile (hi/lo), 128 rows x 64
    #pragma unroll
    for (int t = 0; t < 4; t++) {
        int idx = tid + (t << 8);          // 0..1023
        int row = idx >> 3, c4 = idx & 7;
        size_t go = gq + (size_t)(q0 + row) * HD + c4 * 8;
        *(uint4*)(smem + row*AST + c4*16)            = *(const uint4*)(g_qh + go);
        *(uint4*)(smem + off_Ql + row*AST + c4*16)   = *(const uint4*)(g_ql + go);
    }
    __syncthreads();

    // Q fragments to registers (persist whole kernel)
    uint32_t qfh[4][4], qfl[4][4];
    {
        int arow = wid*16 + (lane & 15);
        #pragma unroll
        for (int ks = 0; ks < 4; ks++) {
            uint32_t a = sb + arow*AST + (ks*16 + (lane >> 4)*8) * 2;
            ldsm4(qfh[ks], a);
            ldsm4(qfl[ks], a + off_Ql);
        }
    }

    float o[8][4];
    #pragma unroll
    for (int i = 0; i < 8; i++)
        #pragma unroll
        for (int e = 0; e < 4; e++) o[i][e] = 0.f;
    float m0 = -1e30f, m1 = -1e30f, l0 = 0.f, l1 = 0.f;

    for (int t = 0; t < SEQ / 64; t++) {
        __syncthreads();   // previous tile's compute done
        #pragma unroll
        for (int it = 0; it < 2; it++) {
            int idx = tid + (it << 8);    // 0..511
            int row = idx >> 3, c4 = idx & 7;
            size_t go = gq + (size_t)(t*64 + row) * HD + c4 * 8;
            uint32_t so = row*AST + c4*16;
            *(uint4*)(smem + off_K + so)         = *(const uint4*)(g_kh + go);
            *(uint4*)(smem + off_K + KTI + so)   = *(const uint4*)(g_kl + go);
            *(uint4*)(smem + off_V + so)         = *(const uint4*)(g_vh + go);
            *(uint4*)(smem + off_V + KTI + so)   = *(const uint4*)(g_vl + go);
        }
        __syncthreads();

        // S = Q K^T   (8 n-tiles of 8 kv)
        float sacc[8][4];
        #pragma unroll
        for (int i = 0; i < 8; i++)
            #pragma unroll
            for (int e = 0; e < 4; e++) sacc[i][e] = 0.f;
        #pragma unroll
        for (int ks = 0; ks < 4; ks++) {
            #pragma unroll
            for (int np = 0; np < 4; np++) {
                int nrow = np*16 + (lane & 7) + ((lane >> 4) & 1) * 8;
                int kcol = ks*16 + ((lane >> 3) & 1) * 8;
                uint32_t a = sb + off_K + nrow*AST + kcol*2;
                uint32_t kbh[4], kbl[4];
                ldsm4(kbh, a); ldsm4(kbl, a + KTI);
                mma16816(sacc[2*np],   qfh[ks], kbh);
                mma16816(sacc[2*np],   qfh[ks], kbl);
                mma16816(sacc[2*np],   qfl[ks], kbh);
                mma16816(sacc[2*np+1], qfh[ks], kbh + 2);
                mma16816(sacc[2*np+1], qfh[ks], kbl + 2);
                mma16816(sacc[2*np+1], qfl[ks], kbh + 2);
            }
        }

        // online softmax (rows r=lane>>2 and r+8; quad reduction)
        float mx0 = sacc[0][0], mx1 = sacc[0][2];
        #pragma unroll
        for (int nt = 0; nt < 8; nt++) {
            mx0 = fmaxf(mx0, fmaxf(sacc[nt][0], sacc[nt][1]));
            mx1 = fmaxf(mx1, fmaxf(sacc[nt][2], sacc[nt][3]));
        }
        mx0 = fmaxf(mx0, __shfl_xor_sync(0xffffffffu, mx0, 1));
        mx0 = fmaxf(mx0, __shfl_xor_sync(0xffffffffu, mx0, 2));
        mx1 = fmaxf(mx1, __shfl_xor_sync(0xffffffffu, mx1, 1));
        mx1 = fmaxf(mx1, __shfl_xor_sync(0xffffffffu, mx1, 2));
        float mn0 = fmaxf(m0, mx0), mn1 = fmaxf(m1, mx1);
        float sc0 = __expf(m0 - mn0), sc1 = __expf(m1 - mn1);
        m0 = mn0; m1 = mn1;
        float s0 = 0.f, s1 = 0.f;
        #pragma unroll
        for (int nt = 0; nt < 8; nt++) {
            sacc[nt][0] = __expf(sacc[nt][0] - mn0);
            sacc[nt][1] = __expf(sacc[nt][1] - mn0);
            sacc[nt][2] = __expf(sacc[nt][2] - mn1);
            sacc[nt][3] = __expf(sacc[nt][3] - mn1);
            s0 += sacc[nt][0] + sacc[nt][1];
            s1 += sacc[nt][2] + sacc[nt][3];
        }
        s0 += __shfl_xor_sync(0xffffffffu, s0, 1);
        s0 += __shfl_xor_sync(0xffffffffu, s0, 2);
        s1 += __shfl_xor_sync(0xffffffffu, s1, 1);
        s1 += __shfl_xor_sync(0xffffffffu, s1, 2);
        l0 = l0 * sc0 + s0;
        l1 = l1 * sc1 + s1;
        #pragma unroll
        for (int nt = 0; nt < 8; nt++) {
            o[nt][0] *= sc0; o[nt][1] *= sc0;
            o[nt][2] *= sc1; o[nt][3] *= sc1;
        }

        // O += P V  (P from sacc; V via ldmatrix.trans)
        #pragma unroll
        for (int kp = 0; kp < 4; kp++) {
            uint32_t pah[4], pal[4];
            {
                float* p0 = sacc[2*kp];
                float* p1 = sacc[2*kp + 1];
                __nv_bfloat16 e;
                float r0, r1;
                e = __float2bfloat16(p0[0]); r0 = p0[0] - __bfloat162float(e);
                __nv_bfloat162 t0; t0.x = e;
                e = __float2bfloat16(p0[1]); r1 = p0[1] - __bfloat162float(e);
                t0.y = e; pah[0] = *(uint32_t*)&t0; pal[0] = bfpair(r0, r1);
                e = __float2bfloat16(p0[2]); r0 = p0[2] - __bfloat162float(e);
                __nv_bfloat162 t1; t1.x = e;
                e = __float2bfloat16(p0[3]); r1 = p0[3] - __bfloat162float(e);
                t1.y = e; pah[1] = *(uint32_t*)&t1; pal[1] = bfpair(r0, r1);
                e = __float2bfloat16(p1[0]); r0 = p1[0] - __bfloat162float(e);
                __nv_bfloat162 t2; t2.x = e;
                e = __float2bfloat16(p1[1]); r1 = p1[1] - __bfloat162float(e);
                t2.y = e; pah[2] = *(uint32_t*)&t2; pal[2] = bfpair(r0, r1);
                e = __float2bfloat16(p1[2]); r0 = p1[2] - __bfloat162float(e);
                __nv_bfloat162 t3; t3.x = e;
                e = __float2bfloat16(p1[3]); r1 = p1[3] - __bfloat162float(e);
                t3.y = e; pah[3] = *(uint32_t*)&t3; pal[3] = bfpair(r0, r1);
            }
            #pragma unroll
            for (int np = 0; np < 4; np++) {
                int krow = kp*16 + (lane & 7) + ((lane >> 3) & 1) * 8;
                int ncol = np*16 + ((lane >> 4) & 1) * 8;
                uint32_t a = sb + off_V + krow*AST + ncol*2;
                uint32_t vbh[4], vbl[4];
                ldsm4t(vbh, a); ldsm4t(vbl, a + KTI);
                mma16816(o[2*np],   pah, vbh);
                mma16816(o[2*np],   pah, vbl);
                mma16816(o[2*np],   pal, vbh);
                mma16816(o[2*np+1], pah, vbh + 2);
                mma16816(o[2*np+1], pah, vbl + 2);
                mma16816(o[2*np+1], pal, vbh + 2);
            }
        }
    }

    // epilogue: O/l -> bf16 hi/lo -> g_ah/g_al [B,S,D]
    float inv0 = 1.f / l0, inv1 = 1.f / l1;
    int r0 = q0 + wid*16 + (lane >> 2);
    int col0 = h * HD + (lane & 3) * 2;
    #pragma unroll
    for (int nt = 0; nt < 8; nt++) {
        int cg = col0 + nt * 8;
        #pragma unroll
        for (int rh = 0; rh < 2; rh++) {
            float inv = rh ? inv1 : inv0;
            float v0 = o[nt][rh*2] * inv, v1 = o[nt][rh*2+1] * inv;
            int s = r0 + rh * 8;
            size_t off = ((size_t)(b * SEQ + s)) * DMODEL + cg;
            __nv_bfloat16 h0 = __float2bfloat16(v0);
            __nv_bfloat16 h1 = __float2bfloat16(v1);
            __nv_bfloat162 hp; hp.x = h0; hp.y = h1;
            uint32_t lp = bfpair(v0 - __bfloat162float(h0),
                                 v1 - __bfloat162float(h1));
            *(uint32_t*)(g_ah + off) = *(uint32_t*)&hp;
            *(uint32_t*)(g_al + off) = lp;
        }
    }
}

// ============================================================================
extern "C" void kernel_launch(void* const* d_in, const int* in_sizes, int n_in,
                              void* d_out, int out_size)
{
    const float* x      = (const float*)d_in[0];
    const float* W_qkv  = (const float*)d_in[1];
    const float* b_qkv  = (const float*)d_in[2];
    const float* W_proj = (const float*)d_in[3];
    const float* b_proj = (const float*)d_in[4];
    float* out = (float*)d_out;

    cudaFuncSetAttribute(gemm_mma<0>,
                         cudaFuncAttributeMaxDynamicSharedMemorySize, SMEM_GEMM);
    cudaFuncSetAttribute(gemm_mma<1>,
                         cudaFuncAttributeMaxDynamicSharedMemorySize, SMEM_GEMM);
    cudaFuncSetAttribute(attn_mma,
                         cudaFuncAttributeMaxDynamicSharedMemorySize, SMEM_ATTN);

    __nv_bfloat16 *xh, *xl, *wqh, *wql, *wph, *wpl, *ah, *al;
    cudaGetSymbolAddress((void**)&xh,  g_xh);
    cudaGetSymbolAddress((void**)&xl,  g_xl);
    cudaGetSymbolAddress((void**)&wqh, g_wqh);
    cudaGetSymbolAddress((void**)&wql, g_wql);
    cudaGetSymbolAddress((void**)&wph, g_wph);
    cudaGetSymbolAddress((void**)&wpl, g_wpl);
    cudaGetSymbolAddress((void**)&ah,  g_ah);
    cudaGetSymbolAddress((void**)&al,  g_al);

    split_x <<<8192, 256>>>(x, xh, xl);
    split_tr<<<dim3(96, 32), 256>>>(W_qkv,  wqh, wql, 3072);
    split_tr<<<dim3(32, 32), 256>>>(W_proj, wph, wpl, 1024);

    gemm_mma<0><<<dim3(24, 64), 256, SMEM_GEMM>>>(xh, xl, wqh, wql, b_qkv, nullptr);
    attn_mma<<<dim3(64, 16), 256, SMEM_ATTN>>>();
    gemm_mma<1><<<dim3(8, 64), 256, SMEM_GEMM>>>(ah, al, wph, wpl, b_proj, out);
}

// round 6
// speedup vs baseline: 3.0644x; 1.1674x over previous
#include <cuda_runtime.h>
#include <cuda_bf16.h>
#include <math.h>
#include <cstdint>

// Problem constants
#define BDIM   4
#define SEQ    2048
#define DMODEL 1024
#define NH     16
#define HD     64
#define SCALE  0.125f            // 1/sqrt(64)

// ============================================================================
// mma.sync / ldmatrix / cp.async helpers (base sm_80+ PTX, compute_103-safe)
// ============================================================================
__device__ __forceinline__ void mma16816(float* c, const uint32_t* a, const uint32_t* b) {
    asm volatile("mma.sync.aligned.m16n8k16.row.col.f32.bf16.bf16.f32 "
        "{%0,%1,%2,%3}, {%4,%5,%6,%7}, {%8,%9}, {%0,%1,%2,%3};"
        : "+f"(c[0]), "+f"(c[1]), "+f"(c[2]), "+f"(c[3])
        : "r"(a[0]), "r"(a[1]), "r"(a[2]), "r"(a[3]), "r"(b[0]), "r"(b[1]));
}
__device__ __forceinline__ void ldsm4(uint32_t* r, uint32_t addr) {
    asm volatile("ldmatrix.sync.aligned.m8n8.x4.shared.b16 {%0,%1,%2,%3}, [%4];"
        : "=r"(r[0]), "=r"(r[1]), "=r"(r[2]), "=r"(r[3]) : "r"(addr));
}
__device__ __forceinline__ void ldsm4t(uint32_t* r, uint32_t addr) {
    asm volatile("ldmatrix.sync.aligned.m8n8.x4.trans.shared.b16 {%0,%1,%2,%3}, [%4];"
        : "=r"(r[0]), "=r"(r[1]), "=r"(r[2]), "=r"(r[3]) : "r"(addr));
}
__device__ __forceinline__ uint32_t smem_u32(const void* p) {
    uint32_t a;
    asm("{ .reg .u64 t; cvta.to.shared.u64 t, %1; cvt.u32.u64 %0, t; }"
        : "=r"(a) : "l"(p));
    return a;
}
__device__ __forceinline__ void cp16(uint32_t s, const void* g) {
    asm volatile("cp.async.cg.shared.global [%0], [%1], 16;" :: "r"(s), "l"(g));
}
#define CP_COMMIT() asm volatile("cp.async.commit_group;" ::: "memory")
#define CP_WAIT(n)  asm volatile("cp.async.wait_group %0;" :: "n"(n) : "memory")

__device__ __forceinline__ uint32_t bfpair(float x, float y) {
    __nv_bfloat162 p;
    p.x = __float2bfloat16(x); p.y = __float2bfloat16(y);
    return *(uint32_t*)&p;
}

// ============================================================================
// scratch (device globals: no allocation allowed)
// ============================================================================
__device__ __nv_bfloat16 g_xh [8192*1024];   // X hi
__device__ __nv_bfloat16 g_xl [8192*1024];   // X lo
__device__ __nv_bfloat16 g_wqh[3072*1024];   // W_qkv^T hi  [N,K]
__device__ __nv_bfloat16 g_wql[3072*1024];
__device__ __nv_bfloat16 g_wph[1024*1024];   // W_proj^T hi [N,K]
__device__ __nv_bfloat16 g_wpl[1024*1024];
__device__ __nv_bfloat16 g_qh[BDIM*NH*SEQ*HD];  // q hi (pre-scaled), [B,H,S,hd]
__device__ __nv_bfloat16 g_ql[BDIM*NH*SEQ*HD];
__device__ __nv_bfloat16 g_kh[BDIM*NH*SEQ*HD];
__device__ __nv_bfloat16 g_kl[BDIM*NH*SEQ*HD];
__device__ __nv_bfloat16 g_vh[BDIM*NH*SEQ*HD];
__device__ __nv_bfloat16 g_vl[BDIM*NH*SEQ*HD];
__device__ __nv_bfloat16 g_ah[8192*1024];    // attn out hi [B,S,D]
__device__ __nv_bfloat16 g_al[8192*1024];

// ============================================================================
// Pre-pass: split X into bf16 hi/lo
// ============================================================================
__global__ __launch_bounds__(256) void split_x(const float* __restrict__ x,
                                               __nv_bfloat16* __restrict__ dh,
                                               __nv_bfloat16* __restrict__ dl)
{
    size_t i = ((size_t)blockIdx.x * 256 + threadIdx.x) * 4;
    float4 v = *(const float4*)(x + i);
    __nv_bfloat16 h0 = __float2bfloat16(v.x);
    __nv_bfloat16 h1 = __float2bfloat16(v.y);
    __nv_bfloat16 h2 = __float2bfloat16(v.z);
    __nv_bfloat16 h3 = __float2bfloat16(v.w);
    __nv_bfloat162 h01, h23, l01, l23;
    h01.x = h0; h01.y = h1; h23.x = h2; h23.y = h3;
    l01.x = __float2bfloat16(v.x - __bfloat162float(h0));
    l01.y = __float2bfloat16(v.y - __bfloat162float(h1));
    l23.x = __float2bfloat16(v.z - __bfloat162float(h2));
    l23.y = __float2bfloat16(v.w - __bfloat162float(h3));
    *(__nv_bfloat162*)(dh + i)     = h01;
    *(__nv_bfloat162*)(dh + i + 2) = h23;
    *(__nv_bfloat162*)(dl + i)     = l01;
    *(__nv_bfloat162*)(dl + i + 2) = l23;
}

// ============================================================================
// Pre-pass: transpose + split W [K=1024, N] -> W^T hi/lo [N, 1024]
// ============================================================================
__global__ __launch_bounds__(256) void split_tr(const float* __restrict__ src,
                                                __nv_bfloat16* __restrict__ dh,
                                                __nv_bfloat16* __restrict__ dl,
                                                int N)
{
    __shared__ float t[32][33];
    const int n0 = blockIdx.x * 32, k0 = blockIdx.y * 32;
    const int tx = threadIdx.x & 31, ty = threadIdx.x >> 5;   // ty 0..7
    #pragma unroll
    for (int r = 0; r < 4; r++) {
        int k = k0 + ty + r * 8;
        t[ty + r * 8][tx] = src[(size_t)k * N + n0 + tx];
    }
    __syncthreads();
    #pragma unroll
    for (int r = 0; r < 4; r++) {
        int n = n0 + ty + r * 8;
        float v = t[tx][ty + r * 8];
        __nv_bfloat16 h = __float2bfloat16(v);
        dh[(size_t)n * 1024 + k0 + tx] = h;
        dl[(size_t)n * 1024 + k0 + tx] = __float2bfloat16(v - __bfloat162float(h));
    }
}

// ============================================================================
// GEMM via mma.sync + cp.async: C[128,128] = A[M,1024] @ B^T, split-bf16.
// BK=32, 2-stage cp.async pipeline, 2 CTAs/SM. 8 warps (2M x 4N), 64x32/warp.
// EPI 0: QKV scatter (bf16 hi/lo q/k/v). EPI 1: proj fp32 out + bias.
// ============================================================================
#define GST    80                 // smem row stride bytes (32 bf16 + pad)
#define GTILE  (128*GST)          // 10240
#define GSTAGE (4*GTILE)          // 40960 (Ah,Al,Bh,Bl)
#define SMEM_GEMM (2*GSTAGE)      // 81920

__device__ __forceinline__ void g_cp(uint32_t sdst, const __nv_bfloat16* __restrict__ g,
                                     int rb, int chunk, int tid)
{
    #pragma unroll
    for (int t = 0; t < 2; t++) {
        int idx = tid + (t << 8);            // 0..511
        int row = idx >> 2, c4 = idx & 3;    // 4 x 16B per 64B row
        cp16(sdst + row * GST + c4 * 16,
             g + (size_t)(rb + row) * 1024 + chunk * 32 + c4 * 8);
    }
}

template<int EPI>
__global__ __launch_bounds__(256, 2)
void gemm_mma(const __nv_bfloat16* __restrict__ Ah_g, const __nv_bfloat16* __restrict__ Al_g,
              const __nv_bfloat16* __restrict__ Bh_g, const __nv_bfloat16* __restrict__ Bl_g,
              const float* __restrict__ bias, float* __restrict__ out)
{
    extern __shared__ char smem[];
    const uint32_t sb = smem_u32(smem);
    const int tid = threadIdx.x, lane = tid & 31, wid = tid >> 5;
    const int bm = blockIdx.y * 128, bn = blockIdx.x * 128;
    const int wm = (wid >> 2) * 64, wn = (wid & 3) * 32;

    float acc[4][4][4];
    #pragma unroll
    for (int i = 0; i < 4; i++)
        #pragma unroll
        for (int j = 0; j < 4; j++)
            #pragma unroll
            for (int e = 0; e < 4; e++) acc[i][j][e] = 0.f;

    // prologue: stage 0 <- chunk 0
    g_cp(sb + 0*GTILE, Ah_g, bm, 0, tid);
    g_cp(sb + 1*GTILE, Al_g, bm, 0, tid);
    g_cp(sb + 2*GTILE, Bh_g, bn, 0, tid);
    g_cp(sb + 3*GTILE, Bl_g, bn, 0, tid);
    CP_COMMIT();

    for (int c = 0; c < 32; c++) {
        if (c < 31) {
            uint32_t nb = sb + ((c + 1) & 1) * GSTAGE;
            g_cp(nb + 0*GTILE, Ah_g, bm, c + 1, tid);
            g_cp(nb + 1*GTILE, Al_g, bm, c + 1, tid);
            g_cp(nb + 2*GTILE, Bh_g, bn, c + 1, tid);
            g_cp(nb + 3*GTILE, Bl_g, bn, c + 1, tid);
            CP_COMMIT();
            CP_WAIT(1);
        } else {
            CP_WAIT(0);
        }
        __syncthreads();

        const uint32_t base = sb + (c & 1) * GSTAGE;
        #pragma unroll
        for (int ks = 0; ks < 2; ks++) {
            const int k0 = ks * 16;
            uint32_t bfh[8], bfl[8];
            #pragma unroll
            for (int np = 0; np < 2; np++) {
                int nrow = wn + np*16 + (lane & 7) + ((lane >> 4) & 1) * 8;
                int kcol = k0 + ((lane >> 3) & 1) * 8;
                uint32_t a = base + 2*GTILE + nrow * GST + kcol * 2;
                ldsm4(&bfh[np*4], a);
                ldsm4(&bfl[np*4], a + GTILE);
            }
            #pragma unroll
            for (int mt = 0; mt < 4; mt++) {
                int arow = wm + mt*16 + (lane & 15);
                int acol = k0 + (lane >> 4) * 8;
                uint32_t aa = base + arow * GST + acol * 2;
                uint32_t afh[4], afl[4];
                ldsm4(afh, aa);
                ldsm4(afl, aa + GTILE);
                #pragma unroll
                for (int nt = 0; nt < 4; nt++) {
                    mma16816(acc[mt][nt], afh, &bfh[nt*2]);
                    mma16816(acc[mt][nt], afh, &bfl[nt*2]);
                    mma16816(acc[mt][nt], afl, &bfh[nt*2]);
                }
            }
        }
        __syncthreads();
    }

    // epilogue
    #pragma unroll
    for (int mt = 0; mt < 4; mt++) {
        #pragma unroll
        for (int nt = 0; nt < 4; nt++) {
            float* cc = acc[mt][nt];
            int ng = bn + wn + nt*8 + (lane & 3) * 2;
            float2 bb = *(const float2*)(bias + ng);
            #pragma unroll
            for (int rh = 0; rh < 2; rh++) {
                int m = bm + wm + mt*16 + (lane >> 2) + rh * 8;
                float v0 = cc[rh*2] + bb.x, v1 = cc[rh*2+1] + bb.y;
                if (EPI == 0) {
                    int w = ng >> 10, hh = (ng >> 6) & 15, d = ng & 63;
                    int b_ = m >> 11, s = m & 2047;
                    size_t idx = ((size_t)((b_*NH + hh) * SEQ + s)) * HD + d;
                    if (w == 0) { v0 *= SCALE; v1 *= SCALE; }
                    __nv_bfloat16 h0 = __float2bfloat16(v0);
                    __nv_bfloat16 h1 = __float2bfloat16(v1);
                    __nv_bfloat162 hp; hp.x = h0; hp.y = h1;
                    uint32_t lp = bfpair(v0 - __bfloat162float(h0),
                                         v1 - __bfloat162float(h1));
                    __nv_bfloat16* dh = (w == 0) ? g_qh : (w == 1) ? g_kh : g_vh;
                    __nv_bfloat16* dl = (w == 0) ? g_ql : (w == 1) ? g_kl : g_vl;
                    *(uint32_t*)(dh + idx) = *(uint32_t*)&hp;
                    *(uint32_t*)(dl + idx) = lp;
                } else {
                    *(float2*)(out + (size_t)m * 1024 + ng) = make_float2(v0, v1);
                }
            }
        }
    }
}

// ============================================================================
// Flash attention via mma.sync + cp.async KV double-buffer.
// Grid (B*H=64, S/128=16). 256 thr = 8 warps, 16 q-rows/warp. KV tiles of 64.
// ============================================================================
#define AST   144                 // smem row stride bytes (64 bf16 + pad)
#define QTI   (128*AST)           // 18432
#define KTI   (64*AST)            // 9216
#define KVSTG (4*KTI)             // 36864 (Kh,Kl,Vh,Vl)
#define SMEM_ATTN (2*QTI + 2*KVSTG)  // 110592

__device__ __forceinline__ void kv_cp(uint32_t sbase, size_t gq, int t, int tid)
{
    #pragma unroll
    for (int it = 0; it < 2; it++) {
        int idx = tid + (it << 8);        // 0..511
        int row = idx >> 3, c8 = idx & 7; // 8 x 16B per 128B row
        size_t go = gq + (size_t)(t*64 + row) * HD + c8 * 8;
        uint32_t so = row * AST + c8 * 16;
        cp16(sbase + 0*KTI + so, g_kh + go);
        cp16(sbase + 1*KTI + so, g_kl + go);
        cp16(sbase + 2*KTI + so, g_vh + go);
        cp16(sbase + 3*KTI + so, g_vl + go);
    }
}

__global__ __launch_bounds__(256)
void attn_mma()
{
    extern __shared__ char smem[];
    const uint32_t sb = smem_u32(smem);
    const int tid = threadIdx.x, lane = tid & 31, wid = tid >> 5;
    const int bh = blockIdx.x, q0 = blockIdx.y * 128;
    const int b = bh >> 4, h = bh & 15;
    const size_t gq = (size_t)bh * SEQ * HD;

    const uint32_t off_Ql = QTI, off_KV = 2*QTI;

    // load Q tile (hi/lo), 128 rows x 64
    #pragma unroll
    for (int t = 0; t < 4; t++) {
        int idx = tid + (t << 8);          // 0..1023
        int row = idx >> 3, c8 = idx & 7;
        size_t go = gq + (size_t)(q0 + row) * HD + c8 * 8;
        *(uint4*)(smem + row*AST + c8*16)          = *(const uint4*)(g_qh + go);
        *(uint4*)(smem + off_Ql + row*AST + c8*16) = *(const uint4*)(g_ql + go);
    }
    // prefetch KV tile 0
    kv_cp(sb + off_KV, gq, 0, tid);
    CP_COMMIT();
    __syncthreads();

    // Q fragments to registers (persist whole kernel)
    uint32_t qfh[4][4], qfl[4][4];
    {
        int arow = wid*16 + (lane & 15);
        #pragma unroll
        for (int ks = 0; ks < 4; ks++) {
            uint32_t a = sb + arow*AST + (ks*16 + (lane >> 4)*8) * 2;
            ldsm4(qfh[ks], a);
            ldsm4(qfl[ks], a + off_Ql);
        }
    }

    float o[8][4];
    #pragma unroll
    for (int i = 0; i < 8; i++)
        #pragma unroll
        for (int e = 0; e < 4; e++) o[i][e] = 0.f;
    float m0 = -1e30f, m1 = -1e30f, l0 = 0.f, l1 = 0.f;

    for (int t = 0; t < SEQ / 64; t++) {
        if (t < SEQ/64 - 1) {
            kv_cp(sb + off_KV + ((t + 1) & 1) * KVSTG, gq, t + 1, tid);
            CP_COMMIT();
            CP_WAIT(1);
        } else {
            CP_WAIT(0);
        }
        __syncthreads();
        const uint32_t kvb = sb + off_KV + (t & 1) * KVSTG;

        // S = Q K^T   (8 n-tiles of 8 kv)
        float sacc[8][4];
        #pragma unroll
        for (int i = 0; i < 8; i++)
            #pragma unroll
            for (int e = 0; e < 4; e++) sacc[i][e] = 0.f;
        #pragma unroll
        for (int ks = 0; ks < 4; ks++) {
            #pragma unroll
            for (int np = 0; np < 4; np++) {
                int nrow = np*16 + (lane & 7) + ((lane >> 4) & 1) * 8;
                int kcol = ks*16 + ((lane >> 3) & 1) * 8;
                uint32_t a = kvb + nrow*AST + kcol*2;
                uint32_t kbh[4], kbl[4];
                ldsm4(kbh, a); ldsm4(kbl, a + KTI);
                mma16816(sacc[2*np],   qfh[ks], kbh);
                mma16816(sacc[2*np],   qfh[ks], kbl);
                mma16816(sacc[2*np],   qfl[ks], kbh);
                mma16816(sacc[2*np+1], qfh[ks], kbh + 2);
                mma16816(sacc[2*np+1], qfh[ks], kbl + 2);
                mma16816(sacc[2*np+1], qfl[ks], kbh + 2);
            }
        }

        // online softmax (rows r=lane>>2 and r+8; quad reduction)
        float mx0 = sacc[0][0], mx1 = sacc[0][2];
        #pragma unroll
        for (int nt = 0; nt < 8; nt++) {
            mx0 = fmaxf(mx0, fmaxf(sacc[nt][0], sacc[nt][1]));
            mx1 = fmaxf(mx1, fmaxf(sacc[nt][2], sacc[nt][3]));
        }
        mx0 = fmaxf(mx0, __shfl_xor_sync(0xffffffffu, mx0, 1));
        mx0 = fmaxf(mx0, __shfl_xor_sync(0xffffffffu, mx0, 2));
        mx1 = fmaxf(mx1, __shfl_xor_sync(0xffffffffu, mx1, 1));
        mx1 = fmaxf(mx1, __shfl_xor_sync(0xffffffffu, mx1, 2));
        float mn0 = fmaxf(m0, mx0), mn1 = fmaxf(m1, mx1);
        float sc0 = __expf(m0 - mn0), sc1 = __expf(m1 - mn1);
        m0 = mn0; m1 = mn1;
        float s0 = 0.f, s1 = 0.f;
        #pragma unroll
        for (int nt = 0; nt < 8; nt++) {
            sacc[nt][0] = __expf(sacc[nt][0] - mn0);
            sacc[nt][1] = __expf(sacc[nt][1] - mn0);
            sacc[nt][2] = __expf(sacc[nt][2] - mn1);
            sacc[nt][3] = __expf(sacc[nt][3] - mn1);
            s0 += sacc[nt][0] + sacc[nt][1];
            s1 += sacc[nt][2] + sacc[nt][3];
        }
        s0 += __shfl_xor_sync(0xffffffffu, s0, 1);
        s0 += __shfl_xor_sync(0xffffffffu, s0, 2);
        s1 += __shfl_xor_sync(0xffffffffu, s1, 1);
        s1 += __shfl_xor_sync(0xffffffffu, s1, 2);
        l0 = l0 * sc0 + s0;
        l1 = l1 * sc1 + s1;
        #pragma unroll
        for (int nt = 0; nt < 8; nt++) {
            o[nt][0] *= sc0; o[nt][1] *= sc0;
            o[nt][2] *= sc1; o[nt][3] *= sc1;
        }

        // O += P V  (P from sacc; V via ldmatrix.trans)
        #pragma unroll
        for (int kp = 0; kp < 4; kp++) {
            uint32_t pah[4], pal[4];
            {
                float* p0 = sacc[2*kp];
                float* p1 = sacc[2*kp + 1];
                __nv_bfloat16 e;
                float r0, r1;
                e = __float2bfloat16(p0[0]); r0 = p0[0] - __bfloat162float(e);
                __nv_bfloat162 t0; t0.x = e;
                e = __float2bfloat16(p0[1]); r1 = p0[1] - __bfloat162float(e);
                t0.y = e; pah[0] = *(uint32_t*)&t0; pal[0] = bfpair(r0, r1);
                e = __float2bfloat16(p0[2]); r0 = p0[2] - __bfloat162float(e);
                __nv_bfloat162 t1; t1.x = e;
                e = __float2bfloat16(p0[3]); r1 = p0[3] - __bfloat162float(e);
                t1.y = e; pah[1] = *(uint32_t*)&t1; pal[1] = bfpair(r0, r1);
                e = __float2bfloat16(p1[0]); r0 = p1[0] - __bfloat162float(e);
                __nv_bfloat162 t2; t2.x = e;
                e = __float2bfloat16(p1[1]); r1 = p1[1] - __bfloat162float(e);
                t2.y = e; pah[2] = *(uint32_t*)&t2; pal[2] = bfpair(r0, r1);
                e = __float2bfloat16(p1[2]); r0 = p1[2] - __bfloat162float(e);
                __nv_bfloat162 t3; t3.x = e;
                e = __float2bfloat16(p1[3]); r1 = p1[3] - __bfloat162float(e);
                t3.y = e; pah[3] = *(uint32_t*)&t3; pal[3] = bfpair(r0, r1);
            }
            #pragma unroll
            for (int np = 0; np < 4; np++) {
                int krow = kp*16 + (lane & 7) + ((lane >> 3) & 1) * 8;
                int ncol = np*16 + ((lane >> 4) & 1) * 8;
                uint32_t a = kvb + 2*KTI + krow*AST + ncol*2;
                uint32_t vbh[4], vbl[4];
                ldsm4t(vbh, a); ldsm4t(vbl, a + KTI);
                mma16816(o[2*np],   pah, vbh);
                mma16816(o[2*np],   pah, vbl);
                mma16816(o[2*np],   pal, vbh);
                mma16816(o[2*np+1], pah, vbh + 2);
                mma16816(o[2*np+1], pah, vbl + 2);
                mma16816(o[2*np+1], pal, vbh + 2);
            }
        }
        __syncthreads();
    }

    // epilogue: O/l -> bf16 hi/lo -> g_ah/g_al [B,S,D]
    float inv0 = 1.f / l0, inv1 = 1.f / l1;
    int r0 = q0 + wid*16 + (lane >> 2);
    int col0 = h * HD + (lane & 3) * 2;
    #pragma unroll
    for (int nt = 0; nt < 8; nt++) {
        int cg = col0 + nt * 8;
        #pragma unroll
        for (int rh = 0; rh < 2; rh++) {
            float inv = rh ? inv1 : inv0;
            float v0 = o[nt][rh*2] * inv, v1 = o[nt][rh*2+1] * inv;
            int s = r0 + rh * 8;
            size_t off = ((size_t)(b * SEQ + s)) * DMODEL + cg;
            __nv_bfloat16 h0 = __float2bfloat16(v0);
            __nv_bfloat16 h1 = __float2bfloat16(v1);
            __nv_bfloat162 hp; hp.x = h0; hp.y = h1;
            uint32_t lp = bfpair(v0 - __bfloat162float(h0),
                                 v1 - __bfloat162float(h1));
            *(uint32_t*)(g_ah + off) = *(uint32_t*)&hp;
            *(uint32_t*)(g_al + off) = lp;
        }
    }
}

// ============================================================================
extern "C" void kernel_launch(void* const* d_in, const int* in_sizes, int n_in,
                              void* d_out, int out_size)
{
    const float* x      = (const float*)d_in[0];
    const float* W_qkv  = (const float*)d_in[1];
    const float* b_qkv  = (const float*)d_in[2];
    const float* W_proj = (const float*)d_in[3];
    const float* b_proj = (const float*)d_in[4];
    float* out = (float*)d_out;

    cudaFuncSetAttribute(gemm_mma<0>,
                         cudaFuncAttributeMaxDynamicSharedMemorySize, SMEM_GEMM);
    cudaFuncSetAttribute(gemm_mma<1>,
                         cudaFuncAttributeMaxDynamicSharedMemorySize, SMEM_GEMM);
    cudaFuncSetAttribute(attn_mma,
                         cudaFuncAttributeMaxDynamicSharedMemorySize, SMEM_ATTN);

    __nv_bfloat16 *xh, *xl, *wqh, *wql, *wph, *wpl, *ah, *al;
    cudaGetSymbolAddress((void**)&xh,  g_xh);
    cudaGetSymbolAddress((void**)&xl,  g_xl);
    cudaGetSymbolAddress((void**)&wqh, g_wqh);
    cudaGetSymbolAddress((void**)&wql, g_wql);
    cudaGetSymbolAddress((void**)&wph, g_wph);
    cudaGetSymbolAddress((void**)&wpl, g_wpl);
    cudaGetSymbolAddress((void**)&ah,  g_ah);
    cudaGetSymbolAddress((void**)&al,  g_al);

    split_x <<<8192, 256>>>(x, xh, xl);
    split_tr<<<dim3(96, 32), 256>>>(W_qkv,  wqh, wql, 3072);
    split_tr<<<dim3(32, 32), 256>>>(W_proj, wph, wpl, 1024);

    gemm_mma<0><<<dim3(24, 64), 256, SMEM_GEMM>>>(xh, xl, wqh, wql, b_qkv, nullptr);
    attn_mma<<<dim3(64, 16), 256, SMEM_ATTN>>>();
    gemm_mma<1><<<dim3(8, 64), 256, SMEM_GEMM>>>(ah, al, wph, wpl, b_proj, out);
}

// round 7
// speedup vs baseline: 3.2165x; 1.0496x over previous
#include <cuda_runtime.h>
#include <cuda_bf16.h>
#include <math.h>
#include <cstdint>

// Problem constants
#define BDIM   4
#define SEQ    2048
#define DMODEL 1024
#define NH     16
#define HD     64
#define SCALE  0.125f            // 1/sqrt(64)

// ============================================================================
// mma.sync / ldmatrix / cp.async helpers (base sm_80+ PTX, compute_103-safe)
// ============================================================================
__device__ __forceinline__ void mma16816(float* c, const uint32_t* a, const uint32_t* b) {
    asm volatile("mma.sync.aligned.m16n8k16.row.col.f32.bf16.bf16.f32 "
        "{%0,%1,%2,%3}, {%4,%5,%6,%7}, {%8,%9}, {%0,%1,%2,%3};"
        : "+f"(c[0]), "+f"(c[1]), "+f"(c[2]), "+f"(c[3])
        : "r"(a[0]), "r"(a[1]), "r"(a[2]), "r"(a[3]), "r"(b[0]), "r"(b[1]));
}
__device__ __forceinline__ void ldsm4(uint32_t* r, uint32_t addr) {
    asm volatile("ldmatrix.sync.aligned.m8n8.x4.shared.b16 {%0,%1,%2,%3}, [%4];"
        : "=r"(r[0]), "=r"(r[1]), "=r"(r[2]), "=r"(r[3]) : "r"(addr));
}
__device__ __forceinline__ void ldsm4t(uint32_t* r, uint32_t addr) {
    asm volatile("ldmatrix.sync.aligned.m8n8.x4.trans.shared.b16 {%0,%1,%2,%3}, [%4];"
        : "=r"(r[0]), "=r"(r[1]), "=r"(r[2]), "=r"(r[3]) : "r"(addr));
}
__device__ __forceinline__ uint32_t smem_u32(const void* p) {
    uint32_t a;
    asm("{ .reg .u64 t; cvta.to.shared.u64 t, %1; cvt.u32.u64 %0, t; }"
        : "=r"(a) : "l"(p));
    return a;
}
__device__ __forceinline__ void cp16(uint32_t s, const void* g) {
    asm volatile("cp.async.cg.shared.global [%0], [%1], 16;" :: "r"(s), "l"(g));
}
#define CP_COMMIT() asm volatile("cp.async.commit_group;" ::: "memory")
#define CP_WAIT(n)  asm volatile("cp.async.wait_group %0;" :: "n"(n) : "memory")

__device__ __forceinline__ uint32_t bfpair(float x, float y) {
    __nv_bfloat162 p;
    p.x = __float2bfloat16(x); p.y = __float2bfloat16(y);
    return *(uint32_t*)&p;
}

// ============================================================================
// scratch (device globals: no allocation allowed)
// ============================================================================
__device__ __nv_bfloat16 g_xh [8192*1024];   // X hi
__device__ __nv_bfloat16 g_xl [8192*1024];   // X lo
__device__ __nv_bfloat16 g_wqh[3072*1024];   // W_qkv^T hi  [N,K]
__device__ __nv_bfloat16 g_wql[3072*1024];
__device__ __nv_bfloat16 g_wph[1024*1024];   // W_proj^T hi [N,K]
__device__ __nv_bfloat16 g_wpl[1024*1024];
__device__ __nv_bfloat16 g_qh[BDIM*NH*SEQ*HD];  // q hi (pre-scaled), [B,H,S,hd]
__device__ __nv_bfloat16 g_ql[BDIM*NH*SEQ*HD];
__device__ __nv_bfloat16 g_kh[BDIM*NH*SEQ*HD];
__device__ __nv_bfloat16 g_kl[BDIM*NH*SEQ*HD];
__device__ __nv_bfloat16 g_vh[BDIM*NH*SEQ*HD];
__device__ __nv_bfloat16 g_vl[BDIM*NH*SEQ*HD];
__device__ __nv_bfloat16 g_ah[8192*1024];    // attn out hi [B,S,D]
__device__ __nv_bfloat16 g_al[8192*1024];

// ============================================================================
// Pre-pass: split X into bf16 hi/lo
// ============================================================================
__global__ __launch_bounds__(256) void split_x(const float* __restrict__ x,
                                               __nv_bfloat16* __restrict__ dh,
                                               __nv_bfloat16* __restrict__ dl)
{
    size_t i = ((size_t)blockIdx.x * 256 + threadIdx.x) * 4;
    float4 v = *(const float4*)(x + i);
    __nv_bfloat16 h0 = __float2bfloat16(v.x);
    __nv_bfloat16 h1 = __float2bfloat16(v.y);
    __nv_bfloat16 h2 = __float2bfloat16(v.z);
    __nv_bfloat16 h3 = __float2bfloat16(v.w);
    __nv_bfloat162 h01, h23, l01, l23;
    h01.x = h0; h01.y = h1; h23.x = h2; h23.y = h3;
    l01.x = __float2bfloat16(v.x - __bfloat162float(h0));
    l01.y = __float2bfloat16(v.y - __bfloat162float(h1));
    l23.x = __float2bfloat16(v.z - __bfloat162float(h2));
    l23.y = __float2bfloat16(v.w - __bfloat162float(h3));
    *(__nv_bfloat162*)(dh + i)     = h01;
    *(__nv_bfloat162*)(dh + i + 2) = h23;
    *(__nv_bfloat162*)(dl + i)     = l01;
    *(__nv_bfloat162*)(dl + i + 2) = l23;
}

// ============================================================================
// Pre-pass: transpose + split W [K=1024, N] -> W^T hi/lo [N, 1024]
// ============================================================================
__global__ __launch_bounds__(256) void split_tr(const float* __restrict__ src,
                                                __nv_bfloat16* __restrict__ dh,
                                                __nv_bfloat16* __restrict__ dl,
                                                int N)
{
    __shared__ float t[32][33];
    const int n0 = blockIdx.x * 32, k0 = blockIdx.y * 32;
    const int tx = threadIdx.x & 31, ty = threadIdx.x >> 5;   // ty 0..7
    #pragma unroll
    for (int r = 0; r < 4; r++) {
        int k = k0 + ty + r * 8;
        t[ty + r * 8][tx] = src[(size_t)k * N + n0 + tx];
    }
    __syncthreads();
    #pragma unroll
    for (int r = 0; r < 4; r++) {
        int n = n0 + ty + r * 8;
        float v = t[tx][ty + r * 8];
        __nv_bfloat16 h = __float2bfloat16(v);
        dh[(size_t)n * 1024 + k0 + tx] = h;
        dl[(size_t)n * 1024 + k0 + tx] = __float2bfloat16(v - __bfloat162float(h));
    }
}

// ============================================================================
// GEMM via mma.sync + cp.async: C[128,128] = A[M,1024] @ B^T, split-bf16.
// BK=32, 2-stage pipeline, ONE sync per chunk, 2 CTAs/SM.
// EPI 0: QKV scatter (bf16 hi/lo q/k/v). EPI 1: proj fp32 out + bias.
// ============================================================================
#define GST    80                 // smem row stride bytes (32 bf16 + pad)
#define GTILE  (128*GST)          // 10240
#define GSTAGE (4*GTILE)          // 40960 (Ah,Al,Bh,Bl)
#define SMEM_GEMM (2*GSTAGE)      // 81920

__device__ __forceinline__ void g_cp(uint32_t sdst, const __nv_bfloat16* __restrict__ g,
                                     int rb, int chunk, int tid)
{
    #pragma unroll
    for (int t = 0; t < 2; t++) {
        int idx = tid + (t << 8);            // 0..511
        int row = idx >> 2, c4 = idx & 3;    // 4 x 16B per 64B row
        cp16(sdst + row * GST + c4 * 16,
             g + (size_t)(rb + row) * 1024 + chunk * 32 + c4 * 8);
    }
}

template<int EPI>
__global__ __launch_bounds__(256, 2)
void gemm_mma(const __nv_bfloat16* __restrict__ Ah_g, const __nv_bfloat16* __restrict__ Al_g,
              const __nv_bfloat16* __restrict__ Bh_g, const __nv_bfloat16* __restrict__ Bl_g,
              const float* __restrict__ bias, float* __restrict__ out)
{
    extern __shared__ char smem[];
    const uint32_t sb = smem_u32(smem);
    const int tid = threadIdx.x, lane = tid & 31, wid = tid >> 5;
    const int bm = blockIdx.y * 128, bn = blockIdx.x * 128;
    const int wm = (wid >> 2) * 64, wn = (wid & 3) * 32;

    float acc[4][4][4];
    #pragma unroll
    for (int i = 0; i < 4; i++)
        #pragma unroll
        for (int j = 0; j < 4; j++)
            #pragma unroll
            for (int e = 0; e < 4; e++) acc[i][j][e] = 0.f;

    // prologue: stage 0 <- chunk 0
    g_cp(sb + 0*GTILE, Ah_g, bm, 0, tid);
    g_cp(sb + 1*GTILE, Al_g, bm, 0, tid);
    g_cp(sb + 2*GTILE, Bh_g, bn, 0, tid);
    g_cp(sb + 3*GTILE, Bl_g, bn, 0, tid);
    CP_COMMIT();

    for (int c = 0; c < 32; c++) {
        CP_WAIT(0);          // chunk c resident
        __syncthreads();     // publish chunk c; retire reads of stage (c+1)&1
        if (c < 31) {        // copies for c+1 overlap compute of c
            uint32_t nb = sb + ((c + 1) & 1) * GSTAGE;
            g_cp(nb + 0*GTILE, Ah_g, bm, c + 1, tid);
            g_cp(nb + 1*GTILE, Al_g, bm, c + 1, tid);
            g_cp(nb + 2*GTILE, Bh_g, bn, c + 1, tid);
            g_cp(nb + 3*GTILE, Bl_g, bn, c + 1, tid);
            CP_COMMIT();
        }

        const uint32_t base = sb + (c & 1) * GSTAGE;
        #pragma unroll
        for (int ks = 0; ks < 2; ks++) {
            const int k0 = ks * 16;
            uint32_t bfh[8], bfl[8];
            #pragma unroll
            for (int np = 0; np < 2; np++) {
                int nrow = wn + np*16 + (lane & 7) + ((lane >> 4) & 1) * 8;
                int kcol = k0 + ((lane >> 3) & 1) * 8;
                uint32_t a = base + 2*GTILE + nrow * GST + kcol * 2;
                ldsm4(&bfh[np*4], a);
                ldsm4(&bfl[np*4], a + GTILE);
            }
            #pragma unroll
            for (int mt = 0; mt < 4; mt++) {
                int arow = wm + mt*16 + (lane & 15);
                int acol = k0 + (lane >> 4) * 8;
                uint32_t aa = base + arow * GST + acol * 2;
                uint32_t afh[4], afl[4];
                ldsm4(afh, aa);
                ldsm4(afl, aa + GTILE);
                #pragma unroll
                for (int nt = 0; nt < 4; nt++) {
                    mma16816(acc[mt][nt], afh, &bfh[nt*2]);
                    mma16816(acc[mt][nt], afh, &bfl[nt*2]);
                    mma16816(acc[mt][nt], afl, &bfh[nt*2]);
                }
            }
        }
    }

    // epilogue
    #pragma unroll
    for (int mt = 0; mt < 4; mt++) {
        #pragma unroll
        for (int nt = 0; nt < 4; nt++) {
            float* cc = acc[mt][nt];
            int ng = bn + wn + nt*8 + (lane & 3) * 2;
            float2 bb = *(const float2*)(bias + ng);
            #pragma unroll
            for (int rh = 0; rh < 2; rh++) {
                int m = bm + wm + mt*16 + (lane >> 2) + rh * 8;
                float v0 = cc[rh*2] + bb.x, v1 = cc[rh*2+1] + bb.y;
                if (EPI == 0) {
                    int w = ng >> 10, hh = (ng >> 6) & 15, d = ng & 63;
                    int b_ = m >> 11, s = m & 2047;
                    size_t idx = ((size_t)((b_*NH + hh) * SEQ + s)) * HD + d;
                    if (w == 0) { v0 *= SCALE; v1 *= SCALE; }
                    __nv_bfloat16 h0 = __float2bfloat16(v0);
                    __nv_bfloat16 h1 = __float2bfloat16(v1);
                    __nv_bfloat162 hp; hp.x = h0; hp.y = h1;
                    uint32_t lp = bfpair(v0 - __bfloat162float(h0),
                                         v1 - __bfloat162float(h1));
                    __nv_bfloat16* dh = (w == 0) ? g_qh : (w == 1) ? g_kh : g_vh;
                    __nv_bfloat16* dl = (w == 0) ? g_ql : (w == 1) ? g_kl : g_vl;
                    *(uint32_t*)(dh + idx) = *(uint32_t*)&hp;
                    *(uint32_t*)(dl + idx) = lp;
                } else {
                    *(float2*)(out + (size_t)m * 1024 + ng) = make_float2(v0, v1);
                }
            }
        }
    }
}

// ============================================================================
// Flash attention, software-pipelined: 3-stage KV ring, dual S accumulators.
// Per tile: issue S(t+1) HMMAs first, run softmax(t) on ALU while tensor
// drains, then PV(t). Grid (B*H=64, S/128=16). 256 thr = 8 warps.
// ============================================================================
#define AST   144                 // smem row stride bytes (64 bf16 + pad)
#define QTI   (128*AST)           // 18432
#define KTI   (64*AST)            // 9216
#define KVSTG (4*KTI)             // 36864 (Kh,Kl,Vh,Vl)
#define NKV   (SEQ/64)            // 32
#define SMEM_ATTN (2*QTI + 3*KVSTG)  // 147456

__device__ __forceinline__ void kv_cp(uint32_t sbase, size_t gq, int t, int tid)
{
    #pragma unroll
    for (int it = 0; it < 2; it++) {
        int idx = tid + (it << 8);        // 0..511
        int row = idx >> 3, c8 = idx & 7; // 8 x 16B per 128B row
        size_t go = gq + (size_t)(t*64 + row) * HD + c8 * 8;
        uint32_t so = row * AST + c8 * 16;
        cp16(sbase + 0*KTI + so, g_kh + go);
        cp16(sbase + 1*KTI + so, g_kl + go);
        cp16(sbase + 2*KTI + so, g_vh + go);
        cp16(sbase + 3*KTI + so, g_vl + go);
    }
}

// S = Q K^T for one KV tile (reads K from kvb)
#define ATTN_S(kvb, SAC) do {                                              \
    _Pragma("unroll")                                                      \
    for (int i = 0; i < 8; i++)                                            \
        _Pragma("unroll")                                                  \
        for (int e = 0; e < 4; e++) (SAC)[i][e] = 0.f;                     \
    _Pragma("unroll")                                                      \
    for (int ks = 0; ks < 4; ks++) {                                       \
        _Pragma("unroll")                                                  \
        for (int np = 0; np < 4; np++) {                                   \
            int nrow = np*16 + (lane & 7) + ((lane >> 4) & 1) * 8;         \
            int kcol = ks*16 + ((lane >> 3) & 1) * 8;                      \
            uint32_t a = (kvb) + nrow*AST + kcol*2;                        \
            uint32_t kbh[4], kbl[4];                                       \
            ldsm4(kbh, a); ldsm4(kbl, a + KTI);                            \
            mma16816((SAC)[2*np],   qfh[ks], kbh);                         \
            mma16816((SAC)[2*np],   qfh[ks], kbl);                         \
            mma16816((SAC)[2*np],   qfl[ks], kbh);                         \
            mma16816((SAC)[2*np+1], qfh[ks], kbh + 2);                     \
            mma16816((SAC)[2*np+1], qfh[ks], kbl + 2);                     \
            mma16816((SAC)[2*np+1], qfl[ks], kbh + 2);                     \
        }                                                                  \
    }                                                                      \
} while (0)

// online softmax on SAC + rescale o
#define ATTN_SOFTMAX(SAC) do {                                             \
    float mx0 = (SAC)[0][0], mx1 = (SAC)[0][2];                            \
    _Pragma("unroll")                                                      \
    for (int nt = 0; nt < 8; nt++) {                                       \
        mx0 = fmaxf(mx0, fmaxf((SAC)[nt][0], (SAC)[nt][1]));               \
        mx1 = fmaxf(mx1, fmaxf((SAC)[nt][2], (SAC)[nt][3]));               \
    }                                                                      \
    mx0 = fmaxf(mx0, __shfl_xor_sync(0xffffffffu, mx0, 1));                \
    mx0 = fmaxf(mx0, __shfl_xor_sync(0xffffffffu, mx0, 2));                \
    mx1 = fmaxf(mx1, __shfl_xor_sync(0xffffffffu, mx1, 1));                \
    mx1 = fmaxf(mx1, __shfl_xor_sync(0xffffffffu, mx1, 2));                \
    float mn0 = fmaxf(m0, mx0), mn1 = fmaxf(m1, mx1);                      \
    float sc0 = __expf(m0 - mn0), sc1 = __expf(m1 - mn1);                  \
    m0 = mn0; m1 = mn1;                                                    \
    float s0 = 0.f, s1 = 0.f;                                              \
    _Pragma("unroll")                                                      \
    for (int nt = 0; nt < 8; nt++) {                                       \
        (SAC)[nt][0] = __expf((SAC)[nt][0] - mn0);                         \
        (SAC)[nt][1] = __expf((SAC)[nt][1] - mn0);                         \
        (SAC)[nt][2] = __expf((SAC)[nt][2] - mn1);                         \
        (SAC)[nt][3] = __expf((SAC)[nt][3] - mn1);                         \
        s0 += (SAC)[nt][0] + (SAC)[nt][1];                                 \
        s1 += (SAC)[nt][2] + (SAC)[nt][3];                                 \
    }                                                                      \
    s0 += __shfl_xor_sync(0xffffffffu, s0, 1);                             \
    s0 += __shfl_xor_sync(0xffffffffu, s0, 2);                             \
    s1 += __shfl_xor_sync(0xffffffffu, s1, 1);                             \
    s1 += __shfl_xor_sync(0xffffffffu, s1, 2);                             \
    l0 = l0 * sc0 + s0;                                                    \
    l1 = l1 * sc1 + s1;                                                    \
    _Pragma("unroll")                                                      \
    for (int nt = 0; nt < 8; nt++) {                                       \
        o[nt][0] *= sc0; o[nt][1] *= sc0;                                  \
        o[nt][2] *= sc1; o[nt][3] *= sc1;                                  \
    }                                                                      \
} while (0)

// O += P V  (P = SAC, V at kvb+2*KTI via ldmatrix.trans)
#define ATTN_PV(kvb, SAC) do {                                             \
    _Pragma("unroll")                                                      \
    for (int kp = 0; kp < 4; kp++) {                                       \
        uint32_t pah[4], pal[4];                                           \
        {                                                                  \
            float* p0 = (SAC)[2*kp];                                       \
            float* p1 = (SAC)[2*kp + 1];                                   \
            __nv_bfloat16 e; float r0, r1;                                 \
            e = __float2bfloat16(p0[0]); r0 = p0[0] - __bfloat162float(e); \
            __nv_bfloat162 t0; t0.x = e;                                   \
            e = __float2bfloat16(p0[1]); r1 = p0[1] - __bfloat162float(e); \
            t0.y = e; pah[0] = *(uint32_t*)&t0; pal[0] = bfpair(r0, r1);   \
            e = __float2bfloat16(p0[2]); r0 = p0[2] - __bfloat162float(e); \
            __nv_bfloat162 t1; t1.x = e;                                   \
            e = __float2bfloat16(p0[3]); r1 = p0[3] - __bfloat162float(e); \
            t1.y = e; pah[1] = *(uint32_t*)&t1; pal[1] = bfpair(r0, r1);   \
            e = __float2bfloat16(p1[0]); r0 = p1[0] - __bfloat162float(e); \
            __nv_bfloat162 t2; t2.x = e;                                   \
            e = __float2bfloat16(p1[1]); r1 = p1[1] - __bfloat162float(e); \
            t2.y = e; pah[2] = *(uint32_t*)&t2; pal[2] = bfpair(r0, r1);   \
            e = __float2bfloat16(p1[2]); r0 = p1[2] - __bfloat162float(e); \
            __nv_bfloat162 t3; t3.x = e;                                   \
            e = __float2bfloat16(p1[3]); r1 = p1[3] - __bfloat162float(e); \
            t3.y = e; pah[3] = *(uint32_t*)&t3; pal[3] = bfpair(r0, r1);   \
        }                                                                  \
        _Pragma("unroll")                                                  \
        for (int np = 0; np < 4; np++) {                                   \
            int krow = kp*16 + (lane & 7) + ((lane >> 3) & 1) * 8;         \
            int ncol = np*16 + ((lane >> 4) & 1) * 8;                      \
            uint32_t a = (kvb) + 2*KTI + krow*AST + ncol*2;                \
            uint32_t vbh[4], vbl[4];                                       \
            ldsm4t(vbh, a); ldsm4t(vbl, a + KTI);                          \
            mma16816(o[2*np],   pah, vbh);                                 \
            mma16816(o[2*np],   pah, vbl);                                 \
            mma16816(o[2*np],   pal, vbh);                                 \
            mma16816(o[2*np+1], pah, vbh + 2);                             \
            mma16816(o[2*np+1], pah, vbl + 2);                             \
            mma16816(o[2*np+1], pal, vbh + 2);                             \
        }                                                                  \
    }                                                                      \
} while (0)

// one pipeline step: S(t+1) issue -> softmax(t) -> PV(t) -> ring rotate
#define ATTN_STEP(T, CUR, NXT) do {                                        \
    __syncthreads();          /* stage kv2 fully retired (PV(T-1) done) */ \
    if ((T) + 2 < NKV) {                                                   \
        kv_cp(kv2, gq, (T) + 2, tid); CP_COMMIT(); CP_WAIT(1);             \
    } else {                                                               \
        CP_WAIT(0);                                                        \
    }                                                                      \
    __syncthreads();          /* KV(T+1) visible to all */                 \
    if ((T) < NKV - 1) { ATTN_S(kv1, NXT); }                               \
    ATTN_SOFTMAX(CUR);                                                     \
    ATTN_PV(kv0, CUR);                                                     \
    { uint32_t r_ = kv0; kv0 = kv1; kv1 = kv2; kv2 = r_; }                 \
} while (0)

__global__ __launch_bounds__(256, 1)
void attn_mma()
{
    extern __shared__ char smem[];
    const uint32_t sb = smem_u32(smem);
    const int tid = threadIdx.x, lane = tid & 31, wid = tid >> 5;
    const int bh = blockIdx.x, q0 = blockIdx.y * 128;
    const int b = bh >> 4, h = bh & 15;
    const size_t gq = (size_t)bh * SEQ * HD;

    const uint32_t off_Ql = QTI, off_KV = 2*QTI;
    uint32_t kv0 = sb + off_KV;            // holds KV(t)
    uint32_t kv1 = kv0 + KVSTG;            // holds KV(t+1)
    uint32_t kv2 = kv0 + 2*KVSTG;          // filling with KV(t+2)

    // prefetch KV(0), KV(1) first so Q's LDG latency overlaps
    kv_cp(kv0, gq, 0, tid); CP_COMMIT();
    kv_cp(kv1, gq, 1, tid); CP_COMMIT();

    // load Q tile (hi/lo), 128 rows x 64
    #pragma unroll
    for (int t = 0; t < 4; t++) {
        int idx = tid + (t << 8);          // 0..1023
        int row = idx >> 3, c8 = idx & 7;
        size_t go = gq + (size_t)(q0 + row) * HD + c8 * 8;
        *(uint4*)(smem + row*AST + c8*16)          = *(const uint4*)(g_qh + go);
        *(uint4*)(smem + off_Ql + row*AST + c8*16) = *(const uint4*)(g_ql + go);
    }
    __syncthreads();

    // Q fragments to registers (persist whole kernel)
    uint32_t qfh[4][4], qfl[4][4];
    {
        int arow = wid*16 + (lane & 15);
        #pragma unroll
        for (int ks = 0; ks < 4; ks++) {
            uint32_t a = sb + arow*AST + (ks*16 + (lane >> 4)*8) * 2;
            ldsm4(qfh[ks], a);
            ldsm4(qfl[ks], a + off_Ql);
        }
    }

    float o[8][4];
    #pragma unroll
    for (int i = 0; i < 8; i++)
        #pragma unroll
        for (int e = 0; e < 4; e++) o[i][e] = 0.f;
    float m0 = -1e30f, m1 = -1e30f, l0 = 0.f, l1 = 0.f;

    float sA[8][4], sB[8][4];

    // KV(0) resident (KV(1) may still be in flight)
    CP_WAIT(1);
    __syncthreads();
    ATTN_S(kv0, sA);

    for (int t = 0; t < NKV; t += 2) {
        ATTN_STEP(t,     sA, sB);
        ATTN_STEP(t + 1, sB, sA);
    }

    // epilogue: O/l -> bf16 hi/lo -> g_ah/g_al [B,S,D]
    float inv0 = 1.f / l0, inv1 = 1.f / l1;
    int r0 = q0 + wid*16 + (lane >> 2);
    int col0 = h * HD + (lane & 3) * 2;
    #pragma unroll
    for (int nt = 0; nt < 8; nt++) {
        int cg = col0 + nt * 8;
        #pragma unroll
        for (int rh = 0; rh < 2; rh++) {
            float inv = rh ? inv1 : inv0;
            float v0 = o[nt][rh*2] * inv, v1 = o[nt][rh*2+1] * inv;
            int s = r0 + rh * 8;
            size_t off = ((size_t)(b * SEQ + s)) * DMODEL + cg;
            __nv_bfloat16 h0 = __float2bfloat16(v0);
            __nv_bfloat16 h1 = __float2bfloat16(v1);
            __nv_bfloat162 hp; hp.x = h0; hp.y = h1;
            uint32_t lp = bfpair(v0 - __bfloat162float(h0),
                                 v1 - __bfloat162float(h1));
            *(uint32_t*)(g_ah + off) = *(uint32_t*)&hp;
            *(uint32_t*)(g_al + off) = lp;
        }
    }
}

// ============================================================================
extern "C" void kernel_launch(void* const* d_in, const int* in_sizes, int n_in,
                              void* d_out, int out_size)
{
    const float* x      = (const float*)d_in[0];
    const float* W_qkv  = (const float*)d_in[1];
    const float* b_qkv  = (const float*)d_in[2];
    const float* W_proj = (const float*)d_in[3];
    const float* b_proj = (const float*)d_in[4];
    float* out = (float*)d_out;

    cudaFuncSetAttribute(gemm_mma<0>,
                         cudaFuncAttributeMaxDynamicSharedMemorySize, SMEM_GEMM);
    cudaFuncSetAttribute(gemm_mma<1>,
                         cudaFuncAttributeMaxDynamicSharedMemorySize, SMEM_GEMM);
    cudaFuncSetAttribute(attn_mma,
                         cudaFuncAttributeMaxDynamicSharedMemorySize, SMEM_ATTN);

    __nv_bfloat16 *xh, *xl, *wqh, *wql, *wph, *wpl, *ah, *al;
    cudaGetSymbolAddress((void**)&xh,  g_xh);
    cudaGetSymbolAddress((void**)&xl,  g_xl);
    cudaGetSymbolAddress((void**)&wqh, g_wqh);
    cudaGetSymbolAddress((void**)&wql, g_wql);
    cudaGetSymbolAddress((void**)&wph, g_wph);
    cudaGetSymbolAddress((void**)&wpl, g_wpl);
    cudaGetSymbolAddress((void**)&ah,  g_ah);
    cudaGetSymbolAddress((void**)&al,  g_al);

    split_x <<<8192, 256>>>(x, xh, xl);
    split_tr<<<dim3(96, 32), 256>>>(W_qkv,  wqh, wql, 3072);
    split_tr<<<dim3(32, 32), 256>>>(W_proj, wph, wpl, 1024);

    gemm_mma<0><<<dim3(24, 64), 256, SMEM_GEMM>>>(xh, xl, wqh, wql, b_qkv, nullptr);
    attn_mma<<<dim3(64, 16), 256, SMEM_ATTN>>>();
    gemm_mma<1><<<dim3(8, 64), 256, SMEM_GEMM>>>(ah, al, wph, wpl, b_proj, out);
}